// round 16
// baseline (speedup 1.0000x reference)
#include <cuda_runtime.h>
#include <math.h>

#define NUM_F 39
#define EMBED 64
#define NUM_P 741            // F*(F-1)/2
#define TPB   256
#define ROW_IN_V4  (NUM_F * EMBED / 4)     // 624 float4 per input row
#define ROW_OUT_V4 (NUM_P * EMBED / 4)     // 11856 float4 per output row

__global__ __launch_bounds__(TPB, 8)       // force <=32 regs -> 8 CTAs/SM
void pairwise_kernel(const float* __restrict__ in, float* __restrict__ out)
{
    __shared__ float4         s[ROW_IN_V4];   // 9984 B: one batch row
    __shared__ unsigned short pij[NUM_P];     // packed pair: i<<8 | j

    const int b   = blockIdx.x;
    const int tid = threadIdx.x;

    // 1) Stage this batch row's input into smem (float4, coalesced)
    const float4* in4 = (const float4*)(in + (size_t)b * NUM_F * EMBED);
    #pragma unroll
    for (int k = tid; k < ROW_IN_V4; k += TPB)
        s[k] = in4[k];

    // 2) Build packed pair table: p -> (i<<8 | j), strict upper triangle,
    //    row-major. offset(i) = i*F - i*(i+1)/2; closed-form inverse + fixup.
    for (int p = tid; p < NUM_P; p += TPB) {
        int i = (int)(38.5f - sqrtf(1482.25f - 2.0f * (float)p)); // F=39
        if (i < 0) i = 0;
        while (i * NUM_F - i * (i + 1) / 2 > p) --i;
        while ((i + 1) * NUM_F - (i + 1) * (i + 2) / 2 <= p) ++i;
        int j = p - (i * NUM_F - i * (i + 1) / 2) + i + 1;
        pij[p] = (unsigned short)((i << 8) | j);   // i in high byte, j low
    }
    __syncthreads();

    // 3) Produce 741*64 outputs as 11856 float4, coalesced streaming stores.
    //    Lanes 0-15 / 16-31 share a pair index (smem broadcast); stores are
    //    perfectly coalesced STG.E.128, 512B contiguous per warp.
    float4* out4 = (float4*)(out + (size_t)b * NUM_P * EMBED);
    const int q = tid & 15;
    int p = tid >> 4;
    #pragma unroll 2
    for (int f = tid; f < ROW_OUT_V4; f += TPB, p += 16) {
        const unsigned int pk = pij[p];
        const float4 a = s[(int)(pk >> 8)   * 16 + q];
        const float4 c = s[(int)(pk & 0xff) * 16 + q];
        float4 r;
        r.x = a.x * c.x;
        r.y = a.y * c.y;
        r.z = a.z * c.z;
        r.w = a.w * c.w;
        __stcs(&out4[f], r);        // streaming: output has zero reuse
    }
}

extern "C" void kernel_launch(void* const* d_in, const int* in_sizes, int n_in,
                              void* d_out, int out_size)
{
    const float* in  = (const float*)d_in[0];
    float*       out = (float*)d_out;
    const int batch  = in_sizes[0] / (NUM_F * EMBED);   // 4096
    pairwise_kernel<<<batch, TPB>>>(in, out);
}

// round 17
// speedup vs baseline: 1.0148x; 1.0148x over previous
#include <cuda_runtime.h>
#include <math.h>

#define NUM_F 39
#define EMBED 64
#define NUM_P 741            // F*(F-1)/2
#define TPB   512
#define ROW_IN_V4  (NUM_F * EMBED / 4)     // 624 float4 per input row
#define ROW_OUT_V4 (NUM_P * EMBED / 4)     // 11856 float4 per output row

__global__ __launch_bounds__(TPB, 4)       // 4 CTAs/SM = 64 warps (same as 256x8)
void pairwise_kernel(const float* __restrict__ in, float* __restrict__ out)
{
    __shared__ float4         s[ROW_IN_V4];   // 9984 B: one batch row
    __shared__ unsigned short pij[NUM_P];     // packed pair: i<<8 | j

    const int b   = blockIdx.x;
    const int tid = threadIdx.x;

    // 1) Stage this batch row's input into smem (float4, coalesced)
    const float4* in4 = (const float4*)(in + (size_t)b * NUM_F * EMBED);
    #pragma unroll
    for (int k = tid; k < ROW_IN_V4; k += TPB)
        s[k] = in4[k];

    // 2) Build packed pair table: p -> (i<<8 | j), strict upper triangle,
    //    row-major. offset(i) = i*F - i*(i+1)/2; closed-form inverse + fixup.
    for (int p = tid; p < NUM_P; p += TPB) {
        int i = (int)(38.5f - sqrtf(1482.25f - 2.0f * (float)p)); // F=39
        if (i < 0) i = 0;
        while (i * NUM_F - i * (i + 1) / 2 > p) --i;
        while ((i + 1) * NUM_F - (i + 1) * (i + 2) / 2 <= p) ++i;
        int j = p - (i * NUM_F - i * (i + 1) / 2) + i + 1;
        pij[p] = (unsigned short)((i << 8) | j);   // i in high byte, j low
    }
    __syncthreads();

    // 3) Produce 741*64 outputs as 11856 float4, coalesced streaming stores.
    //    Lanes 0-15 / 16-31 share a pair index (smem broadcast); stores are
    //    perfectly coalesced STG.E.128, 512B contiguous per warp.
    float4* out4 = (float4*)(out + (size_t)b * NUM_P * EMBED);
    const int q = tid & 15;
    int p = tid >> 4;
    #pragma unroll 2
    for (int f = tid; f < ROW_OUT_V4; f += TPB, p += 32) {
        const unsigned int pk = pij[p];
        const float4 a = s[(int)(pk >> 8)   * 16 + q];
        const float4 c = s[(int)(pk & 0xff) * 16 + q];
        float4 r;
        r.x = a.x * c.x;
        r.y = a.y * c.y;
        r.z = a.z * c.z;
        r.w = a.w * c.w;
        __stcs(&out4[f], r);        // streaming: output has zero reuse
    }
}

extern "C" void kernel_launch(void* const* d_in, const int* in_sizes, int n_in,
                              void* d_out, int out_size)
{
    const float* in  = (const float*)d_in[0];
    float*       out = (float*)d_out;
    const int batch  = in_sizes[0] / (NUM_F * EMBED);   // 4096
    pairwise_kernel<<<batch, TPB>>>(in, out);
}